// round 14
// baseline (speedup 1.0000x reference)
#include <cuda_runtime.h>
#include <cstdint>

#define NB 8
#define S_LEN 4096
#define D 1024
#define D4 (D / 4)        // 256 float4 per row
#define G 128             // persistent grid (<= 148 SMs: one wave, co-resident)
#define T 256
#define SLICES 16         // V row-slices per batch (G = NB * SLICES)
#define ROWS_PER_SLICE (S_LEN / SLICES)  // 256

// Scratch (allocation-free rule: __device__ globals). 16B-aligned for TMA bulk.
__device__ __align__(16) float g_partial[NB * SLICES * D];  // 512 KB
__device__ __align__(16) float g_vsum[NB * D];
__device__ __align__(16) float g_tmp[NB * D];
__device__ unsigned int g_bar[4];  // zero-initialized; monotonic tickets

// xs(32K) + wsv(32K) + wso(32K) + sout(256B)
#define FUSED_SMEM (3 * 2048 * 16 + 256 * 4)

__device__ __forceinline__ void bulk_g2s(uint32_t dst, const void* src,
                                         uint32_t bytes, uint32_t mbar) {
    asm volatile(
        "cp.async.bulk.shared::cta.global.mbarrier::complete_tx::bytes "
        "[%0], [%1], %2, [%3];"
        :: "r"(dst), "l"(src), "r"(bytes), "r"(mbar) : "memory");
}

// Grid barrier: monotonic counter, replay-safe (each replay adds exactly G).
__device__ __forceinline__ void grid_barrier(int i) {
    __threadfence();
    __syncthreads();
    if (threadIdx.x == 0) {
        unsigned int ticket = atomicAdd(&g_bar[i], 1u);
        unsigned int target = (ticket / G + 1u) * G;
        while (atomicAdd(&g_bar[i], 0u) < target) {}
        __threadfence();
    }
    __syncthreads();
}

__global__ void __launch_bounds__(T) fused(const float4* __restrict__ V,
                                           const float4* __restrict__ Wv,
                                           const float*  __restrict__ bv,
                                           const float4* __restrict__ Wo,
                                           const float*  __restrict__ bo,
                                           float* __restrict__ out) {
    extern __shared__ __align__(16) float4 dyn[];
    float4* xs   = dyn;           // 2048 float4: x tile (8 x 256)
    float4* wsv  = dyn + 2048;    // 2048 float4: Wv rows j0..j0+7
    float4* wso  = dyn + 4096;    // 2048 float4: Wo rows j0..j0+7
    float*  sout = reinterpret_cast<float*>(dyn + 6144);
    __shared__ __align__(8) unsigned long long mbar;

    const int t = threadIdx.x;
    const int lane = t & 31;
    const int wid = t >> 5;
    const int b = blockIdx.x;

    const uint32_t mbar_a = (uint32_t)__cvta_generic_to_shared(&mbar);

    // ---- t=0: prefetch this block's W tiles; hides under phase 1 (~20us) ----
    if (t == 0) {
        asm volatile("mbarrier.init.shared.b64 [%0], %1;"
                     :: "r"(mbar_a), "r"(1) : "memory");
        asm volatile("mbarrier.arrive.expect_tx.shared.b64 _, [%0], %1;"
                     :: "r"(mbar_a), "r"(2 * 32768) : "memory");
        bulk_g2s((uint32_t)__cvta_generic_to_shared(wsv),
                 Wv + (size_t)b * 8 * D4, 32768, mbar_a);
        bulk_g2s((uint32_t)__cvta_generic_to_shared(wso),
                 Wo + (size_t)b * 8 * D4, 32768, mbar_a);
    }

    // ---- Phase 1: V column partial sums (the 128 MB HBM read) ----
    // MLP=16: 16 independent in-flight float4 loads per thread
    // (8 warps/SM x 16 = 128 outstanding lines/SM ~= BW*latency requirement).
    {
        const int n = b >> 4;
        const int slice = b & 15;
        const float4* base =
            V + ((size_t)n * S_LEN + (size_t)slice * ROWS_PER_SLICE) * D4 + t;
        float4 a[8];
#pragma unroll
        for (int u = 0; u < 8; ++u) a[u] = make_float4(0.f, 0.f, 0.f, 0.f);

        for (int s = 0; s < ROWS_PER_SLICE; s += 16) {
            float4 v[16];
#pragma unroll
            for (int u = 0; u < 16; ++u)
                v[u] = base[(size_t)(s + u) * D4];   // 16 independent LDGs
#pragma unroll
            for (int u = 0; u < 16; ++u) {
                a[u & 7].x += v[u].x;
                a[u & 7].y += v[u].y;
                a[u & 7].z += v[u].z;
                a[u & 7].w += v[u].w;
            }
        }
#pragma unroll
        for (int u = 4; u > 0; u >>= 1)
#pragma unroll
            for (int k = 0; k < u; ++k) {
                a[k].x += a[k + u].x; a[k].y += a[k + u].y;
                a[k].z += a[k + u].z; a[k].w += a[k + u].w;
            }
        reinterpret_cast<float4*>(g_partial)[(size_t)b * D4 + t] = a[0];
    }

    grid_barrier(0);

    // ---- Phase 2: fold 16 partials per element (16-lane shfl groups) ----
    {
        const int e = b * 16 + (t >> 4);     // element 0..2047 (n*256+col)
        const int s = t & 15;                // which partial slice
        const int n = e >> 8;
        const int col = e & 255;
        float4 v = reinterpret_cast<const float4*>(g_partial)
                       [((size_t)n * 16 + s) * D4 + col];
#pragma unroll
        for (int ofs = 8; ofs > 0; ofs >>= 1) {
            v.x += __shfl_xor_sync(0xFFFFFFFFu, v.x, ofs);
            v.y += __shfl_xor_sync(0xFFFFFFFFu, v.y, ofs);
            v.z += __shfl_xor_sync(0xFFFFFFFFu, v.z, ofs);
            v.w += __shfl_xor_sync(0xFFFFFFFFu, v.w, ofs);
        }
        if (s == 0)
            reinterpret_cast<float4*>(g_vsum)[(size_t)n * D4 + col] = v;
    }

    grid_barrier(1);

    // Wait for W tiles (long since complete — overlapped with phase 1).
    {
        uint32_t done = 0;
        while (!done) {
            asm volatile(
                "{\n\t.reg .pred p;\n\t"
                "mbarrier.try_wait.parity.acquire.cta.shared::cta.b64 p, [%1], %2;\n\t"
                "selp.b32 %0, 1, 0, p;\n\t}"
                : "=r"(done) : "r"(mbar_a), "r"(0) : "memory");
        }
    }
    __syncthreads();

    // ---- Phase 3 + 4: two gemvs against smem-resident W tiles ----
#pragma unroll
    for (int stage = 0; stage < 2; ++stage) {
        const float4* xin = reinterpret_cast<const float4*>(
            stage == 0 ? g_vsum : g_tmp);
        const float4* ws = (stage == 0) ? wsv : wso;
        const float*  bias = (stage == 0) ? bv : bo;
        const float   bscale = (stage == 0) ? (float)S_LEN : 1.0f;
        float* o = (stage == 0) ? g_tmp : out;

        // Stage x (32 KB, L2-hot): 8 float4/thread, coalesced.
#pragma unroll
        for (int i = t; i < NB * D4; i += T) xs[i] = xin[i];
        __syncthreads();

        // Warp wid owns j = b*8 + wid.
        float acc[NB];
#pragma unroll
        for (int n = 0; n < NB; ++n) acc[n] = 0.f;
#pragma unroll
        for (int c = 0; c < 8; ++c) {
            float4 w = ws[wid * D4 + c * 32 + lane];
#pragma unroll
            for (int n = 0; n < NB; ++n) {
                float4 x = xs[n * D4 + c * 32 + lane];
                acc[n] += w.x * x.x + w.y * x.y + w.z * x.z + w.w * x.w;
            }
        }
#pragma unroll
        for (int n = 0; n < NB; ++n) {
#pragma unroll
            for (int ofs = 16; ofs > 0; ofs >>= 1)
                acc[n] += __shfl_xor_sync(0xFFFFFFFFu, acc[n], ofs);
        }
        if (lane == 0) {
#pragma unroll
            for (int n = 0; n < NB; ++n) sout[wid * NB + n] = acc[n];
        }
        __syncthreads();
        if (t < 8 * NB) {
            const int jl = t >> 3;
            const int n  = t & 7;
            const int j  = b * 8 + jl;
            o[n * D + j] = sout[jl * NB + n] + bscale * bias[j];
        }

        if (stage == 0) grid_barrier(2);  // g_tmp fully written before phase 4
    }
}

// ---------------------------------------------------------------------------
extern "C" void kernel_launch(void* const* d_in, const int* in_sizes, int n_in,
                              void* d_out, int out_size) {
    (void)in_sizes; (void)n_in; (void)out_size;
    // metadata order: Q(0) K(1) V(2) Wq(3) bq(4) Wk(5) bk(6) Wv(7) bv(8) Wo(9) bo(10)
    // softmax over a size-1 axis == 1.0 -> Q, K, Wq, bq, Wk, bk are dead inputs.
    const float4* V  = (const float4*)d_in[2];
    const float4* Wv = (const float4*)d_in[7];
    const float*  bv = (const float*)d_in[8];
    const float4* Wo = (const float4*)d_in[9];
    const float*  bo = (const float*)d_in[10];
    float* out = (float*)d_out;

    // Not a stream op; safe under graph capture. Idempotent.
    cudaFuncSetAttribute(fused, cudaFuncAttributeMaxDynamicSharedMemorySize,
                         FUSED_SMEM);

    fused<<<G, T, FUSED_SMEM>>>(V, Wv, bv, Wo, bo, out);
}

// round 16
// speedup vs baseline: 1.4332x; 1.4332x over previous
#include <cuda_runtime.h>
#include <cstdint>

#define NB 8
#define S_LEN 4096
#define D 1024
#define D4 (D / 4)        // 256 float4 per row
#define G 128             // persistent grid (<= 148 SMs: one wave, co-resident)
#define T 1024            // 32 warps/SM -> occ 50%, aggregate MLP >= 256 lines
#define SLICES 16         // V row-slices per batch (G = NB * SLICES)
#define ROWS_PER_SLICE (S_LEN / SLICES)  // 256
#define ROWS_PER_RG (ROWS_PER_SLICE / 4) // 64 rows per row-group

// Scratch (allocation-free rule: __device__ globals). 16B-aligned for TMA bulk.
__device__ __align__(16) float g_partial[NB * SLICES * D];  // 512 KB
__device__ __align__(16) float g_vsum[NB * D];
__device__ __align__(16) float g_tmp[NB * D];
__device__ unsigned int g_bar[4];  // zero-initialized; monotonic tickets

// xs(32K, also reused as phase-1 fold buffer 16K) + wsv(32K) + wso(32K) + sout(1K)
#define FUSED_SMEM (3 * 2048 * 16 + 256 * 4)

__device__ __forceinline__ void bulk_g2s(uint32_t dst, const void* src,
                                         uint32_t bytes, uint32_t mbar) {
    asm volatile(
        "cp.async.bulk.shared::cta.global.mbarrier::complete_tx::bytes "
        "[%0], [%1], %2, [%3];"
        :: "r"(dst), "l"(src), "r"(bytes), "r"(mbar) : "memory");
}

// Grid barrier: monotonic counter, replay-safe (each replay adds exactly G).
__device__ __forceinline__ void grid_barrier(int i) {
    __threadfence();
    __syncthreads();
    if (threadIdx.x == 0) {
        unsigned int ticket = atomicAdd(&g_bar[i], 1u);
        unsigned int target = (ticket / G + 1u) * G;
        while (atomicAdd(&g_bar[i], 0u) < target) {}
        __threadfence();
    }
    __syncthreads();
}

__global__ void __launch_bounds__(T) fused(const float4* __restrict__ V,
                                           const float4* __restrict__ Wv,
                                           const float*  __restrict__ bv,
                                           const float4* __restrict__ Wo,
                                           const float*  __restrict__ bo,
                                           float* __restrict__ out) {
    extern __shared__ __align__(16) float4 dyn[];
    float4* xs   = dyn;           // 2048 float4: x tile / phase-1 fold buffer
    float4* wsv  = dyn + 2048;    // 2048 float4: Wv rows j0..j0+7
    float4* wso  = dyn + 4096;    // 2048 float4: Wo rows j0..j0+7
    float*  sout = reinterpret_cast<float*>(dyn + 6144);  // [4 kq][8 j][8 n]
    __shared__ __align__(8) unsigned long long mbar;

    const int t = threadIdx.x;
    const int lane = t & 31;
    const int wid = t >> 5;      // 0..31
    const int b = blockIdx.x;

    const uint32_t mbar_a = (uint32_t)__cvta_generic_to_shared(&mbar);

    // ---- t=0: prefetch this block's W tiles; hides under phase 1 ----
    if (t == 0) {
        asm volatile("mbarrier.init.shared.b64 [%0], %1;"
                     :: "r"(mbar_a), "r"(1) : "memory");
        asm volatile("mbarrier.arrive.expect_tx.shared.b64 _, [%0], %1;"
                     :: "r"(mbar_a), "r"(2 * 32768) : "memory");
        bulk_g2s((uint32_t)__cvta_generic_to_shared(wsv),
                 Wv + (size_t)b * 8 * D4, 32768, mbar_a);
        bulk_g2s((uint32_t)__cvta_generic_to_shared(wso),
                 Wo + (size_t)b * 8 * D4, 32768, mbar_a);
    }
    __syncthreads();

    // ---- Phase 1: V column partial sums (the 128 MB HBM read) ----
    // 1024 threads = 4 row-groups x 256 cols. Each thread: 64 rows, loads
    // batched by 8 (4 accumulators). 32 warps/SM x MLP8 >= 256 lines in flight.
    {
        const int n = b >> 4;
        const int slice = b & 15;
        const int col = t & 255;
        const int rg  = t >> 8;   // 0..3
        const float4* base = V +
            ((size_t)n * S_LEN + (size_t)slice * ROWS_PER_SLICE +
             (size_t)rg * ROWS_PER_RG) * D4 + col;
        float4 a[4];
#pragma unroll
        for (int u = 0; u < 4; ++u) a[u] = make_float4(0.f, 0.f, 0.f, 0.f);

        for (int s = 0; s < ROWS_PER_RG; s += 8) {
            float4 v[8];
#pragma unroll
            for (int u = 0; u < 8; ++u)
                v[u] = base[(size_t)(s + u) * D4];   // 8 independent LDGs
#pragma unroll
            for (int u = 0; u < 8; ++u) {
                a[u & 3].x += v[u].x; a[u & 3].y += v[u].y;
                a[u & 3].z += v[u].z; a[u & 3].w += v[u].w;
            }
        }
        float4 a0;
        a0.x = (a[0].x + a[1].x) + (a[2].x + a[3].x);
        a0.y = (a[0].y + a[1].y) + (a[2].y + a[3].y);
        a0.z = (a[0].z + a[1].z) + (a[2].z + a[3].z);
        a0.w = (a[0].w + a[1].w) + (a[2].w + a[3].w);

        // Intra-block fold of the 4 row-groups via smem (xs reused).
        xs[rg * 256 + col] = a0;
        __syncthreads();
        if (t < 256) {
            float4 s0 = xs[t], s1 = xs[256 + t], s2 = xs[512 + t], s3 = xs[768 + t];
            float4 r;
            r.x = (s0.x + s1.x) + (s2.x + s3.x);
            r.y = (s0.y + s1.y) + (s2.y + s3.y);
            r.z = (s0.z + s1.z) + (s2.z + s3.z);
            r.w = (s0.w + s1.w) + (s2.w + s3.w);
            reinterpret_cast<float4*>(g_partial)[(size_t)b * D4 + t] = r;
        }
    }

    grid_barrier(0);

    // ---- Phase 2: fold 16 partials per element (16-lane shfl groups) ----
    // Warps 0..7 only (256 threads); full warps active -> shfl mask OK.
    if (t < 256) {
        const int e = b * 16 + (t >> 4);     // element 0..2047 (n*256+col)
        const int s = t & 15;                // which partial slice
        const int n = e >> 8;
        const int col = e & 255;
        float4 v = reinterpret_cast<const float4*>(g_partial)
                       [((size_t)n * 16 + s) * D4 + col];
#pragma unroll
        for (int ofs = 8; ofs > 0; ofs >>= 1) {
            v.x += __shfl_xor_sync(0xFFFFFFFFu, v.x, ofs);
            v.y += __shfl_xor_sync(0xFFFFFFFFu, v.y, ofs);
            v.z += __shfl_xor_sync(0xFFFFFFFFu, v.z, ofs);
            v.w += __shfl_xor_sync(0xFFFFFFFFu, v.w, ofs);
        }
        if (s == 0)
            reinterpret_cast<float4*>(g_vsum)[(size_t)n * D4 + col] = v;
    }

    grid_barrier(1);

    // Wait for W tiles (long since complete — overlapped with phase 1).
    {
        uint32_t done = 0;
        while (!done) {
            asm volatile(
                "{\n\t.reg .pred p;\n\t"
                "mbarrier.try_wait.parity.acquire.cta.shared::cta.b64 p, [%1], %2;\n\t"
                "selp.b32 %0, 1, 0, p;\n\t}"
                : "=r"(done) : "r"(mbar_a), "r"(0) : "memory");
        }
    }
    __syncthreads();

    // ---- Phase 3 + 4: two gemvs against smem-resident W tiles ----
    // 32 warps: jl = wid&7 owns j = b*8+jl, kq = wid>>3 owns 2 k-chunks.
#pragma unroll
    for (int stage = 0; stage < 2; ++stage) {
        const float4* xin = reinterpret_cast<const float4*>(
            stage == 0 ? g_vsum : g_tmp);
        const float4* ws = (stage == 0) ? wsv : wso;
        const float*  bias = (stage == 0) ? bv : bo;
        const float   bscale = (stage == 0) ? (float)S_LEN : 1.0f;
        float* o = (stage == 0) ? g_tmp : out;

        // Stage x (32 KB, L2-hot): 2 float4/thread, coalesced.
        xs[t] = xin[t];
        xs[t + 1024] = xin[t + 1024];
        __syncthreads();

        const int jl = wid & 7;
        const int kq = wid >> 3;   // 0..3

        float acc[NB];
#pragma unroll
        for (int n = 0; n < NB; ++n) acc[n] = 0.f;
#pragma unroll
        for (int ii = 0; ii < 2; ++ii) {
            const int c = kq * 2 + ii;
            float4 w = ws[jl * D4 + c * 32 + lane];
#pragma unroll
            for (int n = 0; n < NB; ++n) {
                float4 x = xs[n * D4 + c * 32 + lane];
                acc[n] += w.x * x.x + w.y * x.y + w.z * x.z + w.w * x.w;
            }
        }
#pragma unroll
        for (int n = 0; n < NB; ++n) {
#pragma unroll
            for (int ofs = 16; ofs > 0; ofs >>= 1)
                acc[n] += __shfl_xor_sync(0xFFFFFFFFu, acc[n], ofs);
        }
        if (lane == 0) {
#pragma unroll
            for (int n = 0; n < NB; ++n)
                sout[kq * 64 + jl * NB + n] = acc[n];
        }
        __syncthreads();
        if (t < 8 * NB) {   // 64 outputs: fold the 4 k-quads
            const int jl2 = t >> 3;
            const int n   = t & 7;
            const int j   = b * 8 + jl2;
            float s = sout[jl2 * NB + n] + sout[64 + jl2 * NB + n] +
                      sout[128 + jl2 * NB + n] + sout[192 + jl2 * NB + n];
            o[n * D + j] = s + bscale * bias[j];
        }

        if (stage == 0) grid_barrier(2);  // g_tmp fully written before phase 4
        else __syncthreads();
    }
}

// ---------------------------------------------------------------------------
extern "C" void kernel_launch(void* const* d_in, const int* in_sizes, int n_in,
                              void* d_out, int out_size) {
    (void)in_sizes; (void)n_in; (void)out_size;
    // metadata order: Q(0) K(1) V(2) Wq(3) bq(4) Wk(5) bk(6) Wv(7) bv(8) Wo(9) bo(10)
    // softmax over a size-1 axis == 1.0 -> Q, K, Wq, bq, Wk, bk are dead inputs.
    const float4* V  = (const float4*)d_in[2];
    const float4* Wv = (const float4*)d_in[7];
    const float*  bv = (const float*)d_in[8];
    const float4* Wo = (const float4*)d_in[9];
    const float*  bo = (const float*)d_in[10];
    float* out = (float*)d_out;

    // Not a stream op; safe under graph capture. Idempotent.
    cudaFuncSetAttribute(fused, cudaFuncAttributeMaxDynamicSharedMemorySize,
                         FUSED_SMEM);

    fused<<<G, T, FUSED_SMEM>>>(V, Wv, bv, Wo, bo, out);
}